// round 3
// baseline (speedup 1.0000x reference)
#include <cuda_runtime.h>
#include <cuda_bf16.h>
#include <math.h>

// Problem constants
#define PB 8
#define PN 256
#define PD 64
#define PE 64
#define PR 32

// ---------------- scratch (no allocations allowed) ----------------
__device__ float g_node[PB * PN * PD];  // LN'd node features
__device__ float g_S[PB * PN * PE];     // node @ Ws + ee_b1   (indexed by j)
__device__ float g_T[PB * PN * PE];     // node @ Wt           (indexed by i)

// 64-thread block reduce (2 warps)
__device__ __forceinline__ float red64(float v, float* s_red) {
#pragma unroll
    for (int o = 16; o; o >>= 1) v += __shfl_xor_sync(0xffffffffu, v, o);
    int w = threadIdx.x >> 5;
    __syncthreads();  // protect s_red reuse across calls
    if ((threadIdx.x & 31) == 0) s_red[w] = v;
    __syncthreads();
    return s_red[0] + s_red[1];
}

// ================= Kernel 1: node embed + LN + S/T precompute =================
__global__ __launch_bounds__(64) void k_node_prep(
    const int* __restrict__ atom, const float* __restrict__ emb,
    const float* __restrict__ ne_w, const float* __restrict__ ne_b,
    const float* __restrict__ ne_g, const float* __restrict__ ne_beta,
    const float* __restrict__ ee_w1, const float* __restrict__ ee_b1)
{
    int row = blockIdx.x;      // b*N + n
    int c = threadIdx.x;       // 0..63
    __shared__ float s_in[64], s_node[64], s_red[2];

    int a = atom[row];
    s_in[c] = fmaxf(emb[a * 64 + c], 0.0f);
    __syncthreads();

    float acc = ne_b[c];
#pragma unroll 8
    for (int k = 0; k < 64; k++) acc += s_in[k] * ne_w[k * 64 + c];

    // two-pass LayerNorm over 64
    float mean = red64(acc, s_red) * (1.0f / 64.0f);
    float d = acc - mean;
    float var = red64(d * d, s_red) * (1.0f / 64.0f);
    float nv = d * rsqrtf(var + 1e-5f) * ne_g[c] + ne_beta[c];

    g_node[row * 64 + c] = nv;
    s_node[c] = nv;
    __syncthreads();

    float sacc = ee_b1[c];   // fold b1 into S
    float tacc = 0.0f;
#pragma unroll 8
    for (int k = 0; k < 64; k++) {
        float x = s_node[k];
        sacc += x * ee_w1[k * 64 + c];          // Ws rows 0..63
        tacc += x * ee_w1[(64 + k) * 64 + c];   // Wt rows 64..127
    }
    g_S[row * 64 + c] = sacc;
    g_T[row * 64 + c] = tacc;
}

// ================= Kernel 2: fused edge MLP =================
// Block per (b,i). 256 threads. Loops over 8 chunks of 32 j's.
// Thread micro-tile: 4 rows (edges) x 2 cols.
__global__ __launch_bounds__(256) void k_edge(
    const float* __restrict__ pos, const float* __restrict__ mask,
    const float* __restrict__ ee_w1,
    const float* __restrict__ ee_w2, const float* __restrict__ ee_b2,
    const float* __restrict__ ee_w3, const float* __restrict__ ee_b3,
    const float* __restrict__ ee_g, const float* __restrict__ ee_beta,
    float* __restrict__ edge_out)
{
    extern __shared__ float sm[];
    float* s_w2  = sm;              // 4096
    float* s_w3  = s_w2 + 4096;     // 4096
    float* s_wr  = s_w3 + 4096;     // 2048 (Wr: rows 128..159 of ee_w1)
    float* s_S   = s_wr + 2048;     // 2048 (32 x 64)
    float* s_h1  = s_S  + 2048;     // 2048 (also reused as 'o')
    float* s_h2  = s_h1 + 2048;     // 2048
    float* s_rbf = s_h2 + 2048;     // 1024 (32 x 32)
    float* s_T   = s_rbf + 1024;    // 64
    float* s_b2  = s_T  + 64;       // 64
    float* s_b3  = s_b2 + 64;       // 64
    float* s_g   = s_b3 + 64;       // 64
    float* s_be  = s_g  + 64;       // 64
    float* s_d   = s_be + 64;       // 32
    float* s_m   = s_d  + 32;       // 32
    // total = 17792 floats = 71168 bytes

    int tid = threadIdx.x;
    int bi = blockIdx.x;            // b*N + i
    int b = bi >> 8;

    for (int idx = tid; idx < 4096; idx += 256) {
        s_w2[idx] = ee_w2[idx];
        s_w3[idx] = ee_w3[idx];
    }
    for (int idx = tid; idx < 2048; idx += 256) s_wr[idx] = ee_w1[128 * 64 + idx];
    if (tid < 64) {
        s_T[tid]  = g_T[bi * 64 + tid];
        s_b2[tid] = ee_b2[tid];
        s_b3[tid] = ee_b3[tid];
        s_g[tid]  = ee_g[tid];
        s_be[tid] = ee_beta[tid];
    }
    float px = pos[bi * 3 + 0];
    float py = pos[bi * 3 + 1];
    float pz = pos[bi * 3 + 2];

    const int c2   = tid & 31;       // col pair
    const int rg   = tid >> 5;       // warp id = row group (4 rows)
    const int c0   = c2 * 2;
    const int lane = tid & 31;

    for (int jc = 0; jc < 8; jc++) {
        int j0 = jc * 32;
        __syncthreads();  // orders prev-iter reads (and initial loads) before refills

        for (int idx = tid; idx < 2048; idx += 256)
            s_S[idx] = g_S[(b * 256 + j0) * 64 + idx];

        if (tid < 32) {
            int j = j0 + tid;
            float qx = pos[(b * 256 + j) * 3 + 0];
            float qy = pos[(b * 256 + j) * 3 + 1];
            float qz = pos[(b * 256 + j) * 3 + 2];
            float dx = px - qx, dy = py - qy, dz = pz - qz;
            float mk = mask[bi * 256 + j];
            s_d[tid] = sqrtf(dx * dx + dy * dy + dz * dz + 1e-10f) * mk;
            s_m[tid] = mk;
        }
        __syncthreads();

        // RBF: 32 edges x 32 features. mu_r = 20*r/31, sigma = 0.625
        for (int idx = tid; idx < 1024; idx += 256) {
            int e = idx >> 5, r = idx & 31;
            float t = (s_d[e] - (20.0f / 31.0f) * (float)r) * 1.6f;
            s_rbf[idx] = __expf(-t * t) * s_m[e];
        }
        __syncthreads();

        // ---- GEMM1: h1 = relu(T[i] + S[j] + rbf @ Wr)   (K = 32) ----
        {
            float acc[4][2];
#pragma unroll
            for (int rr = 0; rr < 4; rr++) {
                int row = rg * 4 + rr;
                acc[rr][0] = s_T[c0]     + s_S[row * 64 + c0];
                acc[rr][1] = s_T[c0 + 1] + s_S[row * 64 + c0 + 1];
            }
#pragma unroll
            for (int r = 0; r < 32; r += 2) {
                float2 w0 = *(const float2*)&s_wr[r * 64 + c0];
                float2 w1 = *(const float2*)&s_wr[(r + 1) * 64 + c0];
#pragma unroll
                for (int rr = 0; rr < 4; rr++) {
                    float2 a = *(const float2*)&s_rbf[(rg * 4 + rr) * 32 + r];
                    acc[rr][0] += a.x * w0.x + a.y * w1.x;
                    acc[rr][1] += a.x * w0.y + a.y * w1.y;
                }
            }
#pragma unroll
            for (int rr = 0; rr < 4; rr++) {
                int row = rg * 4 + rr;
                s_h1[row * 64 + c0]     = fmaxf(acc[rr][0], 0.0f);
                s_h1[row * 64 + c0 + 1] = fmaxf(acc[rr][1], 0.0f);
            }
        }
        __syncthreads();

        // ---- GEMM2: h2 = relu(h1 @ w2 + b2)   (K = 64) ----
        {
            float acc[4][2];
#pragma unroll
            for (int rr = 0; rr < 4; rr++) {
                acc[rr][0] = s_b2[c0];
                acc[rr][1] = s_b2[c0 + 1];
            }
#pragma unroll 8
            for (int k = 0; k < 64; k += 2) {
                float2 w0 = *(const float2*)&s_w2[k * 64 + c0];
                float2 w1 = *(const float2*)&s_w2[(k + 1) * 64 + c0];
#pragma unroll
                for (int rr = 0; rr < 4; rr++) {
                    float2 a = *(const float2*)&s_h1[(rg * 4 + rr) * 64 + k];
                    acc[rr][0] += a.x * w0.x + a.y * w1.x;
                    acc[rr][1] += a.x * w0.y + a.y * w1.y;
                }
            }
#pragma unroll
            for (int rr = 0; rr < 4; rr++) {
                int row = rg * 4 + rr;
                s_h2[row * 64 + c0]     = fmaxf(acc[rr][0], 0.0f);
                s_h2[row * 64 + c0 + 1] = fmaxf(acc[rr][1], 0.0f);
            }
        }
        __syncthreads();

        // ---- GEMM3: o = h2 @ w3 + b3 (no relu), into s_h1 (h1 dead) ----
        {
            float acc[4][2];
#pragma unroll
            for (int rr = 0; rr < 4; rr++) {
                acc[rr][0] = s_b3[c0];
                acc[rr][1] = s_b3[c0 + 1];
            }
#pragma unroll 8
            for (int k = 0; k < 64; k += 2) {
                float2 w0 = *(const float2*)&s_w3[k * 64 + c0];
                float2 w1 = *(const float2*)&s_w3[(k + 1) * 64 + c0];
#pragma unroll
                for (int rr = 0; rr < 4; rr++) {
                    float2 a = *(const float2*)&s_h2[(rg * 4 + rr) * 64 + k];
                    acc[rr][0] += a.x * w0.x + a.y * w1.x;
                    acc[rr][1] += a.x * w0.y + a.y * w1.y;
                }
            }
#pragma unroll
            for (int rr = 0; rr < 4; rr++) {
                int row = rg * 4 + rr;
                s_h1[row * 64 + c0]     = acc[rr][0];
                s_h1[row * 64 + c0 + 1] = acc[rr][1];
            }
        }
        __syncwarp();  // warp rg owns rows rg*4..rg*4+3 entirely — warp-local LN

        // ---- LayerNorm (per row, 64 wide) + store ----
        const float* o = s_h1;
#pragma unroll
        for (int rr = 0; rr < 4; rr++) {
            int row = rg * 4 + rr;
            float x0 = o[row * 64 + lane];
            float x1 = o[row * 64 + lane + 32];
            float s = x0 + x1;
#pragma unroll
            for (int off = 16; off; off >>= 1) s += __shfl_xor_sync(0xffffffffu, s, off);
            float mean = s * (1.0f / 64.0f);
            float d0 = x0 - mean, d1 = x1 - mean;
            float q = d0 * d0 + d1 * d1;
#pragma unroll
            for (int off = 16; off; off >>= 1) q += __shfl_xor_sync(0xffffffffu, q, off);
            float inv = rsqrtf(q * (1.0f / 64.0f) + 1e-5f);
            int base = (bi * 256 + (j0 + row)) * 64;
            edge_out[base + lane]      = d0 * inv * s_g[lane]      + s_be[lane];
            edge_out[base + lane + 32] = d1 * inv * s_g[lane + 32] + s_be[lane + 32];
        }
    }
}

// ================= Kernel 3: aggregation + node MLP + residual =================
__global__ __launch_bounds__(64) void k_agg_node(
    const int* __restrict__ atom, const float* __restrict__ mask,
    const float* __restrict__ na_w1, const float* __restrict__ na_b1,
    const float* __restrict__ na_w2, const float* __restrict__ na_b2,
    const float* __restrict__ na_w3, const float* __restrict__ na_b3,
    const float* __restrict__ na_g, const float* __restrict__ na_beta,
    const float* __restrict__ edge, float* __restrict__ node_out)
{
    int bj = blockIdx.x;        // b*N + j
    int b = bj >> 8, j = bj & 255;
    int c = threadIdx.x;        // 0..63
    __shared__ float s_x[128], s_h[64], s_h2[64], s_red[2];

    // agg[b,j,c] = sum_i edge[b,i,j,c] / (sum_i mask[b,i,j] + 1e-10) * gate
    float acc = 0.0f, msum = 0.0f;
    const float* ep = edge + (b * 65536 + j) * 64 + c;
    const float* mp = mask + b * 65536 + j;
#pragma unroll 4
    for (int i = 0; i < 256; i++) {
        acc  += ep[i * 16384];   // i*256*64
        msum += mp[i * 256];
    }
    float gate = (atom[bj] >= 1) ? 1.0f : 0.0f;
    float nodev = g_node[bj * 64 + c];
    s_x[c]      = nodev;
    s_x[64 + c] = acc / (msum + 1e-10f) * gate;
    __syncthreads();

    float y = na_b1[c];
#pragma unroll 8
    for (int k = 0; k < 128; k++) y += s_x[k] * na_w1[k * 64 + c];
    s_h[c] = fmaxf(y, 0.0f);
    __syncthreads();

    y = na_b2[c];
#pragma unroll 8
    for (int k = 0; k < 64; k++) y += s_h[k] * na_w2[k * 64 + c];
    s_h2[c] = fmaxf(y, 0.0f);
    __syncthreads();

    y = na_b3[c];
#pragma unroll 8
    for (int k = 0; k < 64; k++) y += s_h2[k] * na_w3[k * 64 + c];

    float mean = red64(y, s_red) * (1.0f / 64.0f);
    float d = y - mean;
    float var = red64(d * d, s_red) * (1.0f / 64.0f);
    node_out[bj * 64 + c] = nodev + d * rsqrtf(var + 1e-5f) * na_g[c] + na_beta[c];
}

// ================= launch =================
extern "C" void kernel_launch(void* const* d_in, const int* in_sizes, int n_in,
                              void* d_out, int out_size) {
    (void)in_sizes; (void)n_in; (void)out_size;
    const int*   atom    = (const int*)  d_in[0];
    const float* pos     = (const float*)d_in[1];
    const float* mask    = (const float*)d_in[2];
    const float* emb     = (const float*)d_in[3];
    const float* ne_w    = (const float*)d_in[4];
    const float* ne_b    = (const float*)d_in[5];
    const float* ne_g    = (const float*)d_in[6];
    const float* ne_beta = (const float*)d_in[7];
    const float* ee_w1   = (const float*)d_in[8];
    const float* ee_b1   = (const float*)d_in[9];
    const float* ee_w2   = (const float*)d_in[10];
    const float* ee_b2   = (const float*)d_in[11];
    const float* ee_w3   = (const float*)d_in[12];
    const float* ee_b3   = (const float*)d_in[13];
    const float* ee_g    = (const float*)d_in[14];
    const float* ee_beta = (const float*)d_in[15];
    const float* na_w1   = (const float*)d_in[16];
    const float* na_b1   = (const float*)d_in[17];
    const float* na_w2   = (const float*)d_in[18];
    const float* na_b2   = (const float*)d_in[19];
    const float* na_w3   = (const float*)d_in[20];
    const float* na_b3   = (const float*)d_in[21];
    const float* na_g    = (const float*)d_in[22];
    const float* na_beta = (const float*)d_in[23];

    float* out      = (float*)d_out;
    float* node_out = out;                       // (B,N,D)
    float* edge_out = out + PB * PN * PD;        // (B,N,N,E)

    const size_t SMEM_EDGE = 17792 * sizeof(float);  // 71168 B
    cudaFuncSetAttribute(k_edge, cudaFuncAttributeMaxDynamicSharedMemorySize,
                         (int)SMEM_EDGE);

    k_node_prep<<<PB * PN, 64>>>(atom, emb, ne_w, ne_b, ne_g, ne_beta, ee_w1, ee_b1);
    k_edge<<<PB * PN, 256, SMEM_EDGE>>>(pos, mask, ee_w1, ee_w2, ee_b2,
                                        ee_w3, ee_b3, ee_g, ee_beta, edge_out);
    k_agg_node<<<PB * PN, 64>>>(atom, mask, na_w1, na_b1, na_w2, na_b2,
                                na_w3, na_b3, na_g, na_beta, edge_out, node_out);
}

// round 5
// speedup vs baseline: 1.1636x; 1.1636x over previous
#include <cuda_runtime.h>
#include <cuda_bf16.h>
#include <math.h>

#define PB 8
#define PN 256
#define PD 64
#define PE 64
#define PR 32

// ---------------- scratch (no allocations allowed) ----------------
__device__ float g_node[PB * PN * PD];  // LN'd node features
__device__ float g_S[PB * PN * PE];     // node @ Ws + ee_b1   (indexed by j)
__device__ float g_T[PB * PN * PE];     // node @ Wt           (indexed by i)

// ================= Kernel 1: node embed + LN + S/T precompute =================
// block (64,4): 4 rows per block
__global__ __launch_bounds__(256) void k_node_prep(
    const int* __restrict__ atom, const float* __restrict__ emb,
    const float* __restrict__ ne_w, const float* __restrict__ ne_b,
    const float* __restrict__ ne_g, const float* __restrict__ ne_beta,
    const float* __restrict__ ee_w1, const float* __restrict__ ee_b1)
{
    int y = threadIdx.y;                 // 0..3
    int c = threadIdx.x;                 // 0..63
    int row = blockIdx.x * 4 + y;        // b*N + n
    __shared__ float s_in[4][64], s_node[4][64], s_red[4][2];

    int a = atom[row];
    s_in[y][c] = fmaxf(emb[a * 64 + c], 0.0f);
    __syncthreads();

    float acc = ne_b[c];
#pragma unroll 8
    for (int k = 0; k < 64; k++) acc += s_in[y][k] * ne_w[k * 64 + c];

    // two-pass LN over 64 (2 warps per row)
    float v = acc;
#pragma unroll
    for (int o = 16; o; o >>= 1) v += __shfl_xor_sync(0xffffffffu, v, o);
    if ((c & 31) == 0) s_red[y][c >> 5] = v;
    __syncthreads();
    float mean = (s_red[y][0] + s_red[y][1]) * (1.0f / 64.0f);
    float d = acc - mean;
    v = d * d;
#pragma unroll
    for (int o = 16; o; o >>= 1) v += __shfl_xor_sync(0xffffffffu, v, o);
    __syncthreads();
    if ((c & 31) == 0) s_red[y][c >> 5] = v;
    __syncthreads();
    float var = (s_red[y][0] + s_red[y][1]) * (1.0f / 64.0f);
    float nv = d * rsqrtf(var + 1e-5f) * ne_g[c] + ne_beta[c];

    g_node[row * 64 + c] = nv;
    s_node[y][c] = nv;
    __syncthreads();

    float sacc = ee_b1[c];   // fold b1 into S
    float tacc = 0.0f;
#pragma unroll 8
    for (int k = 0; k < 64; k++) {
        float x = s_node[y][k];
        sacc += x * ee_w1[k * 64 + c];          // Ws rows 0..63
        tacc += x * ee_w1[(64 + k) * 64 + c];   // Wt rows 64..127
    }
    g_S[row * 64 + c] = sacc;
    g_T[row * 64 + c] = tacc;
}

// ================= Kernel 2: fused edge MLP =================
// Block per (b,i). 256 threads. 4 chunks of 64 j's. Micro-tile 4 rows x 4 cols.
#define H_STR 68   // padded row stride for h1/h2 (float4-aligned, bank-shifted)
#define R_STR 36   // padded row stride for rbf (float2-aligned, bank-shifted)

__global__ __launch_bounds__(256) void k_edge(
    const float* __restrict__ pos, const float* __restrict__ mask,
    const float* __restrict__ ee_w1,
    const float* __restrict__ ee_w2, const float* __restrict__ ee_b2,
    const float* __restrict__ ee_w3, const float* __restrict__ ee_b3,
    const float* __restrict__ ee_g, const float* __restrict__ ee_beta,
    float* __restrict__ edge_out)
{
    extern __shared__ float sm[];
    float* s_w2  = sm;                  // 4096
    float* s_w3  = s_w2 + 4096;         // 4096
    float* s_wr  = s_w3 + 4096;         // 2048 (Wr: rows 128..159 of ee_w1)
    float* s_S   = s_wr + 2048;         // 4096 (64 x 64)
    float* s_h1  = s_S  + 4096;         // 64 x H_STR = 4352
    float* s_h2  = s_h1 + 64 * H_STR;   // 4352
    float* s_rbf = s_h2 + 64 * H_STR;   // 64 x R_STR = 2304
    float* s_d   = s_rbf + 64 * R_STR;  // 64
    float* s_m   = s_d + 64;            // 64
    // total = 25472 floats = 101888 bytes

    const int tid = threadIdx.x;
    const int bi = blockIdx.x;          // b*N + i
    const int b = bi >> 8;

    const int cg = tid & 15;            // col group 0..15
    const int c4 = cg * 4;
    const int rg = tid >> 4;            // row group 0..15
    const int r4 = rg * 4;

    // stage weights (once per block)
    for (int idx = tid; idx < 1024; idx += 256) {
        ((float4*)s_w2)[idx] = ((const float4*)ee_w2)[idx];
        ((float4*)s_w3)[idx] = ((const float4*)ee_w3)[idx];
    }
    for (int idx = tid; idx < 512; idx += 256)
        ((float4*)s_wr)[idx] = ((const float4*)(ee_w1 + 128 * 64))[idx];

    // per-thread constants straight from gmem (L1/L2 cached)
    const float4 t4  = *(const float4*)&g_T[bi * 64 + c4];
    const float4 b2v = *(const float4*)&ee_b2[c4];
    const float4 b3v = *(const float4*)&ee_b3[c4];
    const float4 g4  = *(const float4*)&ee_g[c4];
    const float4 be4 = *(const float4*)&ee_beta[c4];

    const float px = pos[bi * 3 + 0];
    const float py = pos[bi * 3 + 1];
    const float pz = pos[bi * 3 + 2];

    for (int jc = 0; jc < 4; jc++) {
        const int j0 = jc * 64;
        __syncthreads();  // protect prev-iter smem reads before refills

        // S tile for this 64-j chunk
        {
            const float4* src = (const float4*)(g_S + (b * 256 + j0) * 64);
            for (int idx = tid; idx < 1024; idx += 256)
                ((float4*)s_S)[idx] = src[idx];
        }
        if (tid < 64) {
            int j = j0 + tid;
            float qx = pos[(b * 256 + j) * 3 + 0];
            float qy = pos[(b * 256 + j) * 3 + 1];
            float qz = pos[(b * 256 + j) * 3 + 2];
            float dx = px - qx, dy = py - qy, dz = pz - qz;
            float mk = mask[bi * 256 + j];
            s_d[tid] = sqrtf(dx * dx + dy * dy + dz * dz + 1e-10f) * mk;
            s_m[tid] = mk;
        }
        __syncthreads();

        // RBF: 64 edges x 32 features. mu_r = 20*r/31, 1/sigma = 1.6
        for (int idx = tid; idx < 2048; idx += 256) {
            int e = idx >> 5, r = idx & 31;
            float t = (s_d[e] - (20.0f / 31.0f) * (float)r) * 1.6f;
            s_rbf[e * R_STR + r] = __expf(-t * t) * s_m[e];
        }
        __syncthreads();

        // ---- GEMM1: h1 = relu(T[i] + S[j] + rbf @ Wr)  (K = 32) ----
        {
            float acc[4][4];
#pragma unroll
            for (int rr = 0; rr < 4; rr++) {
                float4 sv = *(const float4*)&s_S[(r4 + rr) * 64 + c4];
                acc[rr][0] = t4.x + sv.x;
                acc[rr][1] = t4.y + sv.y;
                acc[rr][2] = t4.z + sv.z;
                acc[rr][3] = t4.w + sv.w;
            }
#pragma unroll 4
            for (int k = 0; k < 32; k += 2) {
                float4 w0 = *(const float4*)&s_wr[k * 64 + c4];
                float4 w1 = *(const float4*)&s_wr[(k + 1) * 64 + c4];
#pragma unroll
                for (int rr = 0; rr < 4; rr++) {
                    float2 a = *(const float2*)&s_rbf[(r4 + rr) * R_STR + k];
                    acc[rr][0] += a.x * w0.x + a.y * w1.x;
                    acc[rr][1] += a.x * w0.y + a.y * w1.y;
                    acc[rr][2] += a.x * w0.z + a.y * w1.z;
                    acc[rr][3] += a.x * w0.w + a.y * w1.w;
                }
            }
#pragma unroll
            for (int rr = 0; rr < 4; rr++) {
                float4 o;
                o.x = fmaxf(acc[rr][0], 0.0f);
                o.y = fmaxf(acc[rr][1], 0.0f);
                o.z = fmaxf(acc[rr][2], 0.0f);
                o.w = fmaxf(acc[rr][3], 0.0f);
                *(float4*)&s_h1[(r4 + rr) * H_STR + c4] = o;
            }
        }
        __syncthreads();

        // ---- GEMM2: h2 = relu(h1 @ w2 + b2)  (K = 64) ----
        {
            float acc[4][4];
#pragma unroll
            for (int rr = 0; rr < 4; rr++) {
                acc[rr][0] = b2v.x; acc[rr][1] = b2v.y;
                acc[rr][2] = b2v.z; acc[rr][3] = b2v.w;
            }
#pragma unroll 4
            for (int k = 0; k < 64; k += 2) {
                float4 w0 = *(const float4*)&s_w2[k * 64 + c4];
                float4 w1 = *(const float4*)&s_w2[(k + 1) * 64 + c4];
#pragma unroll
                for (int rr = 0; rr < 4; rr++) {
                    float2 a = *(const float2*)&s_h1[(r4 + rr) * H_STR + k];
                    acc[rr][0] += a.x * w0.x + a.y * w1.x;
                    acc[rr][1] += a.x * w0.y + a.y * w1.y;
                    acc[rr][2] += a.x * w0.z + a.y * w1.z;
                    acc[rr][3] += a.x * w0.w + a.y * w1.w;
                }
            }
#pragma unroll
            for (int rr = 0; rr < 4; rr++) {
                float4 o;
                o.x = fmaxf(acc[rr][0], 0.0f);
                o.y = fmaxf(acc[rr][1], 0.0f);
                o.z = fmaxf(acc[rr][2], 0.0f);
                o.w = fmaxf(acc[rr][3], 0.0f);
                *(float4*)&s_h2[(r4 + rr) * H_STR + c4] = o;
            }
        }
        __syncthreads();

        // ---- GEMM3: o = h2 @ w3 + b3 (stays in registers) ----
        float acc[4][4];
#pragma unroll
        for (int rr = 0; rr < 4; rr++) {
            acc[rr][0] = b3v.x; acc[rr][1] = b3v.y;
            acc[rr][2] = b3v.z; acc[rr][3] = b3v.w;
        }
#pragma unroll 4
        for (int k = 0; k < 64; k += 2) {
            float4 w0 = *(const float4*)&s_w3[k * 64 + c4];
            float4 w1 = *(const float4*)&s_w3[(k + 1) * 64 + c4];
#pragma unroll
            for (int rr = 0; rr < 4; rr++) {
                float2 a = *(const float2*)&s_h2[(r4 + rr) * H_STR + k];
                acc[rr][0] += a.x * w0.x + a.y * w1.x;
                acc[rr][1] += a.x * w0.y + a.y * w1.y;
                acc[rr][2] += a.x * w0.z + a.y * w1.z;
                acc[rr][3] += a.x * w0.w + a.y * w1.w;
            }
        }

        // ---- LayerNorm over 64 cols: 16-lane shfl reduce (4 cols/thread x 16 lanes)
        // lanes [0,16) and [16,32) are independent row groups; offsets 8..1 don't mix them.
#pragma unroll
        for (int rr = 0; rr < 4; rr++) {
            float s = acc[rr][0] + acc[rr][1] + acc[rr][2] + acc[rr][3];
#pragma unroll
            for (int o = 8; o; o >>= 1) s += __shfl_xor_sync(0xffffffffu, s, o);
            float mean = s * (1.0f / 64.0f);
            float d0 = acc[rr][0] - mean, d1 = acc[rr][1] - mean;
            float d2 = acc[rr][2] - mean, d3 = acc[rr][3] - mean;
            float q = d0 * d0 + d1 * d1 + d2 * d2 + d3 * d3;
#pragma unroll
            for (int o = 8; o; o >>= 1) q += __shfl_xor_sync(0xffffffffu, q, o);
            float inv = rsqrtf(q * (1.0f / 64.0f) + 1e-5f);
            float4 o4;
            o4.x = d0 * inv * g4.x + be4.x;
            o4.y = d1 * inv * g4.y + be4.y;
            o4.z = d2 * inv * g4.z + be4.z;
            o4.w = d3 * inv * g4.w + be4.w;
            *(float4*)&edge_out[(bi * 256 + (j0 + r4 + rr)) * 64 + c4] = o4;
        }
    }
}

// ================= Kernel 3: aggregation + node MLP + residual =================
__device__ __forceinline__ float red64(float v, float* s_red) {
#pragma unroll
    for (int o = 16; o; o >>= 1) v += __shfl_xor_sync(0xffffffffu, v, o);
    int w = threadIdx.x >> 5;
    __syncthreads();
    if ((threadIdx.x & 31) == 0) s_red[w] = v;
    __syncthreads();
    return s_red[0] + s_red[1];
}

__global__ __launch_bounds__(64) void k_agg_node(
    const int* __restrict__ atom, const float* __restrict__ mask,
    const float* __restrict__ na_w1, const float* __restrict__ na_b1,
    const float* __restrict__ na_w2, const float* __restrict__ na_b2,
    const float* __restrict__ na_w3, const float* __restrict__ na_b3,
    const float* __restrict__ na_g, const float* __restrict__ na_beta,
    const float* __restrict__ edge, float* __restrict__ node_out)
{
    int bj = blockIdx.x;        // b*N + j
    int b = bj >> 8, j = bj & 255;
    int c = threadIdx.x;        // 0..63
    __shared__ float s_x[128], s_h[64], s_h2[64], s_red[2];

    float acc = 0.0f, msum = 0.0f;
    const float* ep = edge + (b * 65536 + j) * 64 + c;
    const float* mp = mask + b * 65536 + j;
#pragma unroll 8
    for (int i = 0; i < 256; i++) {
        acc  += ep[i * 16384];
        msum += mp[i * 256];
    }
    float gate = (atom[bj] >= 1) ? 1.0f : 0.0f;
    float nodev = g_node[bj * 64 + c];
    s_x[c]      = nodev;
    s_x[64 + c] = acc / (msum + 1e-10f) * gate;
    __syncthreads();

    float y = na_b1[c];
#pragma unroll 8
    for (int k = 0; k < 128; k++) y += s_x[k] * na_w1[k * 64 + c];
    s_h[c] = fmaxf(y, 0.0f);
    __syncthreads();

    y = na_b2[c];
#pragma unroll 8
    for (int k = 0; k < 64; k++) y += s_h[k] * na_w2[k * 64 + c];
    s_h2[c] = fmaxf(y, 0.0f);
    __syncthreads();

    y = na_b3[c];
#pragma unroll 8
    for (int k = 0; k < 64; k++) y += s_h2[k] * na_w3[k * 64 + c];

    float mean = red64(y, s_red) * (1.0f / 64.0f);
    float d = y - mean;
    float var = red64(d * d, s_red) * (1.0f / 64.0f);
    node_out[bj * 64 + c] = nodev + d * rsqrtf(var + 1e-5f) * na_g[c] + na_beta[c];
}

// ================= launch =================
extern "C" void kernel_launch(void* const* d_in, const int* in_sizes, int n_in,
                              void* d_out, int out_size) {
    (void)in_sizes; (void)n_in; (void)out_size;
    const int*   atom    = (const int*)  d_in[0];
    const float* pos     = (const float*)d_in[1];
    const float* mask    = (const float*)d_in[2];
    const float* emb     = (const float*)d_in[3];
    const float* ne_w    = (const float*)d_in[4];
    const float* ne_b    = (const float*)d_in[5];
    const float* ne_g    = (const float*)d_in[6];
    const float* ne_beta = (const float*)d_in[7];
    const float* ee_w1   = (const float*)d_in[8];
    const float* ee_b1   = (const float*)d_in[9];
    const float* ee_w2   = (const float*)d_in[10];
    const float* ee_b2   = (const float*)d_in[11];
    const float* ee_w3   = (const float*)d_in[12];
    const float* ee_b3   = (const float*)d_in[13];
    const float* ee_g    = (const float*)d_in[14];
    const float* ee_beta = (const float*)d_in[15];
    const float* na_w1   = (const float*)d_in[16];
    const float* na_b1   = (const float*)d_in[17];
    const float* na_w2   = (const float*)d_in[18];
    const float* na_b2   = (const float*)d_in[19];
    const float* na_w3   = (const float*)d_in[20];
    const float* na_b3   = (const float*)d_in[21];
    const float* na_g    = (const float*)d_in[22];
    const float* na_beta = (const float*)d_in[23];

    float* out      = (float*)d_out;
    float* node_out = out;                       // (B,N,D)
    float* edge_out = out + PB * PN * PD;        // (B,N,N,E)

    const size_t SMEM_EDGE = 25472 * sizeof(float);  // 101888 B
    cudaFuncSetAttribute(k_edge, cudaFuncAttributeMaxDynamicSharedMemorySize,
                         (int)SMEM_EDGE);

    k_node_prep<<<PB * PN / 4, dim3(64, 4)>>>(atom, emb, ne_w, ne_b, ne_g,
                                              ne_beta, ee_w1, ee_b1);
    k_edge<<<PB * PN, 256, SMEM_EDGE>>>(pos, mask, ee_w1, ee_w2, ee_b2,
                                        ee_w3, ee_b3, ee_g, ee_beta, edge_out);
    k_agg_node<<<PB * PN, 64>>>(atom, mask, na_w1, na_b1, na_w2, na_b2,
                                na_w3, na_b3, na_g, na_beta, edge_out, node_out);
}

// round 8
// speedup vs baseline: 1.8484x; 1.5886x over previous
#include <cuda_runtime.h>
#include <cuda_bf16.h>
#include <math.h>
#include <stdint.h>

#define PB 8
#define PN 256

// ---------------- scratch ----------------
__device__ float g_node[PB * PN * 64];
__device__ float g_T[PB * PN * 64];
__device__ __align__(16) uint32_t g_node_h[PB * PN * 32];
__device__ __align__(16) uint32_t g_node_l[PB * PN * 32];
// fragment-ordered bf16x2 weight images: W1(h,l) W2(h,l) W3(h,l)
__device__ __align__(16) uint32_t g_wimg[14336];

#define W1H_O 0
#define W1L_O 3072
#define W2H_O 6144
#define W2L_O 8192
#define W3H_O 10240
#define W3L_O 12288
#define WIMG_WORDS 14336

#define A_STR 52            // padded A row stride (words)
#define AH_O  WIMG_WORDS    // smem word offsets
#define AL_O  (WIMG_WORDS + 128 * A_STR)
#define SMEM_WORDS (WIMG_WORDS + 2 * 128 * A_STR)   // 27648 words = 110592 B

// res.lo = x0, res.hi = x1
#define PACK_BF16X2(res, x0, x1) \
    asm("cvt.rn.satfinite.bf16x2.f32 %0, %1, %2;" : "=r"(res) : "f"(x1), "f"(x0))

#define MMA_BF16(c, a, b0, b1) \
    asm volatile("mma.sync.aligned.m16n8k16.row.col.f32.bf16.bf16.f32 " \
        "{%0,%1,%2,%3}, {%4,%5,%6,%7}, {%8,%9}, {%0,%1,%2,%3};" \
        : "+f"((c)[0]), "+f"((c)[1]), "+f"((c)[2]), "+f"((c)[3]) \
        : "r"((a)[0]), "r"((a)[1]), "r"((a)[2]), "r"((a)[3]), "r"(b0), "r"(b1))

// exp(-x) for x >= 0, poly exp2, rel err ~1.5e-4 (no MUFU)
__device__ __forceinline__ float fexp_neg(float x) {
    float y = -x * 1.44269504f;
    if (y < -126.0f) return 0.0f;
    float n = floorf(y);
    float f = y - n;
    float p = 1.0f + f * (0.6931472f + f * (0.2402265f + f * (0.0555041f +
              f * (0.0096181f + f * 0.0013333f))));
    return p * __int_as_float(((int)n + 127) << 23);
}

// ================= Kernel 1: node embed + LN + T + bf16 hi/lo pack =================
__global__ __launch_bounds__(256) void k_node_prep(
    const int* __restrict__ atom, const float* __restrict__ emb,
    const float* __restrict__ ne_w, const float* __restrict__ ne_b,
    const float* __restrict__ ne_g, const float* __restrict__ ne_beta,
    const float* __restrict__ ee_w1)
{
    int y = threadIdx.y, c = threadIdx.x;
    int row = blockIdx.x * 4 + y;
    __shared__ float s_in[4][64], s_node[4][64], s_red[4][2];

    int a = atom[row];
    s_in[y][c] = fmaxf(emb[a * 64 + c], 0.0f);
    __syncthreads();

    float acc = ne_b[c];
#pragma unroll 8
    for (int k = 0; k < 64; k++) acc += s_in[y][k] * ne_w[k * 64 + c];

    float v = acc;
#pragma unroll
    for (int o = 16; o; o >>= 1) v += __shfl_xor_sync(0xffffffffu, v, o);
    if ((c & 31) == 0) s_red[y][c >> 5] = v;
    __syncthreads();
    float mean = (s_red[y][0] + s_red[y][1]) * (1.0f / 64.0f);
    float d = acc - mean;
    v = d * d;
#pragma unroll
    for (int o = 16; o; o >>= 1) v += __shfl_xor_sync(0xffffffffu, v, o);
    __syncthreads();
    if ((c & 31) == 0) s_red[y][c >> 5] = v;
    __syncthreads();
    float var = (s_red[y][0] + s_red[y][1]) * (1.0f / 64.0f);
    float nv = d * rsqrtf(var + 1e-5f) * ne_g[c] + ne_beta[c];

    g_node[row * 64 + c] = nv;
    s_node[y][c] = nv;
    __syncthreads();

    float tacc = 0.0f;
#pragma unroll 8
    for (int k = 0; k < 64; k++) tacc += s_node[y][k] * ee_w1[(64 + k) * 64 + c];
    g_T[row * 64 + c] = tacc;

    if (c < 32) {
        float x0 = s_node[y][2 * c], x1 = s_node[y][2 * c + 1];
        uint32_t hi, lo;
        PACK_BF16X2(hi, x0, x1);
        float l0 = x0 - __bfloat162float(__float2bfloat16_rn(x0));
        float l1 = x1 - __bfloat162float(__float2bfloat16_rn(x1));
        PACK_BF16X2(lo, l0, l1);
        g_node_h[row * 32 + c] = hi;
        g_node_l[row * 32 + c] = lo;
    }
}

// ================= Kernel 1b: fragment-ordered weight images =================
// For each layer: word index = ((t*S + s)*2 + reg)*32 + lane
//   k = s*16 + (lane%4)*2 + reg*8 (+0,1 packed), n = t*8 + lane/4
__device__ __forceinline__ void wimg_put(uint32_t* hdst, uint32_t* ldst,
                                         float w0, float w1) {
    uint32_t hw, lw;
    PACK_BF16X2(hw, w0, w1);
    float l0 = w0 - __bfloat162float(__float2bfloat16_rn(w0));
    float l1 = w1 - __bfloat162float(__float2bfloat16_rn(w1));
    PACK_BF16X2(lw, l0, l1);
    *hdst = hw; *ldst = lw;
}

__global__ __launch_bounds__(256) void k_wprep(
    const float* __restrict__ ee_w1, const float* __restrict__ ee_w2,
    const float* __restrict__ ee_w3)
{
    int tid = threadIdx.x;
    // Layer 1: S=6, K=96: k<32 -> Wr (ee_w1 rows 128..159), else Ws (rows 0..63)
    for (int idx = tid; idx < 3072; idx += 256) {
        int lane = idx & 31, reg = (idx >> 5) & 1;
        int ts = idx >> 6;              // t*6 + s
        int s = ts % 6, t = ts / 6;
        int k = s * 16 + (lane & 3) * 2 + reg * 8;
        int n = t * 8 + (lane >> 2);
        float w0 = (k < 32)     ? ee_w1[(128 + k) * 64 + n] : ee_w1[(k - 32) * 64 + n];
        float w1 = (k + 1 < 32) ? ee_w1[(129 + k) * 64 + n] : ee_w1[(k - 31) * 64 + n];
        wimg_put(&g_wimg[W1H_O + idx], &g_wimg[W1L_O + idx], w0, w1);
    }
    // Layers 2/3: S=4, K=64
    for (int idx = tid; idx < 2048; idx += 256) {
        int lane = idx & 31, reg = (idx >> 5) & 1;
        int ts = idx >> 6;
        int s = ts & 3, t = ts >> 2;
        int k = s * 16 + (lane & 3) * 2 + reg * 8;
        int n = t * 8 + (lane >> 2);
        wimg_put(&g_wimg[W2H_O + idx], &g_wimg[W2L_O + idx],
                 ee_w2[k * 64 + n], ee_w2[(k + 1) * 64 + n]);
        wimg_put(&g_wimg[W3H_O + idx], &g_wimg[W3L_O + idx],
                 ee_w3[k * 64 + n], ee_w3[(k + 1) * 64 + n]);
    }
}

// ---- one MLP layer on the tensor pipe (per-warp 16 rows x 64 cols) ----
template <int S>
__device__ __forceinline__ void do_layer(
    const uint32_t* __restrict__ sAh, const uint32_t* __restrict__ sAl,
    const uint32_t* __restrict__ wh, const uint32_t* __restrict__ wl,
    int rb, int lane, float c[8][4])
{
    uint32_t ah[S][4], al[S][4];
    const uint32_t* r0h = sAh + rb * A_STR;
    const uint32_t* r1h = sAh + (rb + 8) * A_STR;
    const uint32_t* r0l = sAl + rb * A_STR;
    const uint32_t* r1l = sAl + (rb + 8) * A_STR;
    const int cw = lane & 3;
#pragma unroll
    for (int s = 0; s < S; s++) {
        ah[s][0] = r0h[s * 8 + cw];     ah[s][1] = r1h[s * 8 + cw];
        ah[s][2] = r0h[s * 8 + 4 + cw]; ah[s][3] = r1h[s * 8 + 4 + cw];
        al[s][0] = r0l[s * 8 + cw];     al[s][1] = r1l[s * 8 + cw];
        al[s][2] = r0l[s * 8 + 4 + cw]; al[s][3] = r1l[s * 8 + 4 + cw];
    }
#pragma unroll
    for (int t = 0; t < 8; t++) {
#pragma unroll
        for (int s = 0; s < S; s++) {
            uint32_t bh0 = wh[((t * S + s) * 2 + 0) * 32 + lane];
            uint32_t bh1 = wh[((t * S + s) * 2 + 1) * 32 + lane];
            uint32_t bl0 = wl[((t * S + s) * 2 + 0) * 32 + lane];
            uint32_t bl1 = wl[((t * S + s) * 2 + 1) * 32 + lane];
            MMA_BF16(c[t], ah[s], bh0, bh1);
            MMA_BF16(c[t], al[s], bh0, bh1);
            MMA_BF16(c[t], ah[s], bl0, bl1);
        }
    }
}

// ---- epilogue: bias + relu + hi/lo split back into A buffer ----
__device__ __forceinline__ void epi_write(
    float c[8][4], const float* __restrict__ bias,
    uint32_t* __restrict__ sAh, uint32_t* __restrict__ sAl, int rb, int lane)
{
    uint32_t* w0h = sAh + rb * A_STR;
    uint32_t* w1h = sAh + (rb + 8) * A_STR;
    uint32_t* w0l = sAl + rb * A_STR;
    uint32_t* w1l = sAl + (rb + 8) * A_STR;
    const int cw = lane & 3;
#pragma unroll
    for (int t = 0; t < 8; t++) {
        float2 bv = *(const float2*)&bias[t * 8 + cw * 2];
        float x0 = fmaxf(c[t][0] + bv.x, 0.0f);
        float x1 = fmaxf(c[t][1] + bv.y, 0.0f);
        float x2 = fmaxf(c[t][2] + bv.x, 0.0f);
        float x3 = fmaxf(c[t][3] + bv.y, 0.0f);
        uint32_t h, l;
        PACK_BF16X2(h, x0, x1);
        float e0 = x0 - __bfloat162float(__float2bfloat16_rn(x0));
        float e1 = x1 - __bfloat162float(__float2bfloat16_rn(x1));
        PACK_BF16X2(l, e0, e1);
        w0h[t * 4 + cw] = h; w0l[t * 4 + cw] = l;
        PACK_BF16X2(h, x2, x3);
        e0 = x2 - __bfloat162float(__float2bfloat16_rn(x2));
        e1 = x3 - __bfloat162float(__float2bfloat16_rn(x3));
        PACK_BF16X2(l, e0, e1);
        w1h[t * 4 + cw] = h; w1l[t * 4 + cw] = l;
    }
}

// ================= Kernel 2: mma.sync edge MLP =================
// Block per (b,i), 256 threads (8 warps x 16 rows), 2 chunks of 128 j's.
__global__ __launch_bounds__(256) void k_edge(
    const float* __restrict__ pos, const float* __restrict__ mask,
    const float* __restrict__ ee_b1, const float* __restrict__ ee_b2,
    const float* __restrict__ ee_b3, const float* __restrict__ ee_g,
    const float* __restrict__ ee_beta, float* __restrict__ edge_out)
{
    extern __shared__ uint32_t sw[];
    __shared__ float s_Tp[64], s_b2[64], s_b3[64], s_g[64], s_be[64];

    const int tid = threadIdx.x;
    const int wid = tid >> 5;
    const int lane = tid & 31;
    const int bi = blockIdx.x;
    const int b = bi >> 8;

    // stage weight images once
    {
        const uint4* src = (const uint4*)g_wimg;
        uint4* dst = (uint4*)sw;
        for (int i = tid; i < WIMG_WORDS / 4; i += 256) dst[i] = src[i];
    }
    if (tid < 64) {
        s_Tp[tid] = g_T[bi * 64 + tid] + ee_b1[tid];
        s_b2[tid] = ee_b2[tid];
        s_b3[tid] = ee_b3[tid];
        s_g[tid]  = ee_g[tid];
        s_be[tid] = ee_beta[tid];
    }

    uint32_t* sAh = sw + AH_O;
    uint32_t* sAl = sw + AL_O;

    const float px = pos[bi * 3 + 0];
    const float py = pos[bi * 3 + 1];
    const float pz = pos[bi * 3 + 2];

    const int rb = wid * 16 + (lane >> 2);   // this lane's base row (and rb+8)

    for (int jc = 0; jc < 2; jc++) {
        const int j0 = jc * 128;
        __syncthreads();   // weights staged / previous chunk fully consumed

        // ---- build A1 = [rbf(32) | node(64)] for rows 0..127 ----
        if (tid < 128) {
            const int row = tid;
            const int gj = b * 256 + j0 + row;
            float qx = pos[gj * 3 + 0], qy = pos[gj * 3 + 1], qz = pos[gj * 3 + 2];
            float mk = mask[bi * 256 + j0 + row];
            float dx = px - qx, dy = py - qy, dz = pz - qz;
            float dist = sqrtf(dx * dx + dy * dy + dz * dz + 1e-10f) * mk;
            uint32_t* rh = sAh + row * A_STR;
            uint32_t* rl = sAl + row * A_STR;
#pragma unroll
            for (int w = 0; w < 16; w++) {
                float t0 = (dist - (20.0f / 31.0f) * (float)(2 * w)) * 1.6f;
                float t1 = (dist - (20.0f / 31.0f) * (float)(2 * w + 1)) * 1.6f;
                float x0 = fexp_neg(t0 * t0) * mk;
                float x1 = fexp_neg(t1 * t1) * mk;
                uint32_t h, l;
                PACK_BF16X2(h, x0, x1);
                float e0 = x0 - __bfloat162float(__float2bfloat16_rn(x0));
                float e1 = x1 - __bfloat162float(__float2bfloat16_rn(x1));
                PACK_BF16X2(l, e0, e1);
                rh[w] = h; rl[w] = l;
            }
            const uint4* nh = (const uint4*)(g_node_h + gj * 32);
            const uint4* nl = (const uint4*)(g_node_l + gj * 32);
#pragma unroll
            for (int q = 0; q < 8; q++) {
                *(uint4*)&rh[16 + 4 * q] = nh[q];
                *(uint4*)&rl[16 + 4 * q] = nl[q];
            }
        }
        __syncthreads();

        // ---- layer 1 (K=96) ----
        {
            float c[8][4] = {};
            do_layer<6>(sAh, sAl, sw + W1H_O, sw + W1L_O, rb, lane, c);
            epi_write(c, s_Tp, sAh, sAl, rb, lane);
        }
        __syncwarp();
        // ---- layer 2 (K=64) ----
        {
            float c[8][4] = {};
            do_layer<4>(sAh, sAl, sw + W2H_O, sw + W2L_O, rb, lane, c);
            epi_write(c, s_b2, sAh, sAl, rb, lane);
        }
        __syncwarp();
        // ---- layer 3 (K=64) + LayerNorm + store ----
        {
            float c[8][4] = {};
            do_layer<4>(sAh, sAl, sw + W3H_O, sw + W3L_O, rb, lane, c);
            const int cw = lane & 3;
#pragma unroll
            for (int t = 0; t < 8; t++) {
                float2 bv = *(const float2*)&s_b3[t * 8 + cw * 2];
                c[t][0] += bv.x; c[t][1] += bv.y;
                c[t][2] += bv.x; c[t][3] += bv.y;
            }
            float s0 = 0.0f, s1 = 0.0f;
#pragma unroll
            for (int t = 0; t < 8; t++) { s0 += c[t][0] + c[t][1]; s1 += c[t][2] + c[t][3]; }
            s0 += __shfl_xor_sync(0xffffffffu, s0, 1);
            s0 += __shfl_xor_sync(0xffffffffu, s0, 2);
            s1 += __shfl_xor_sync(0xffffffffu, s1, 1);
            s1 += __shfl_xor_sync(0xffffffffu, s1, 2);
            float m0 = s0 * (1.0f / 64.0f), m1 = s1 * (1.0f / 64.0f);
            float q0 = 0.0f, q1 = 0.0f;
#pragma unroll
            for (int t = 0; t < 8; t++) {
                float d0 = c[t][0] - m0, d1 = c[t][1] - m0;
                float d2 = c[t][2] - m1, d3 = c[t][3] - m1;
                q0 += d0 * d0 + d1 * d1;
                q1 += d2 * d2 + d3 * d3;
            }
            q0 += __shfl_xor_sync(0xffffffffu, q0, 1);
            q0 += __shfl_xor_sync(0xffffffffu, q0, 2);
            q1 += __shfl_xor_sync(0xffffffffu, q1, 1);
            q1 += __shfl_xor_sync(0xffffffffu, q1, 2);
            float i0 = rsqrtf(q0 * (1.0f / 64.0f) + 1e-5f);
            float i1 = rsqrtf(q1 * (1.0f / 64.0f) + 1e-5f);
            float* d0p = edge_out + (size_t)(bi * 256 + j0 + rb) * 64;
            float* d1p = d0p + 8 * 64;
#pragma unroll
            for (int t = 0; t < 8; t++) {
                int n = t * 8 + cw * 2;
                float2 gv = *(const float2*)&s_g[n];
                float2 bev = *(const float2*)&s_be[n];
                float2 o0, o1;
                o0.x = (c[t][0] - m0) * i0 * gv.x + bev.x;
                o0.y = (c[t][1] - m0) * i0 * gv.y + bev.y;
                o1.x = (c[t][2] - m1) * i1 * gv.x + bev.x;
                o1.y = (c[t][3] - m1) * i1 * gv.y + bev.y;
                *(float2*)&d0p[n] = o0;
                *(float2*)&d1p[n] = o1;
            }
        }
    }
}

// ================= Kernel 3: aggregation + node MLP + residual =================
__device__ __forceinline__ float red64(float v, float* s_red) {
#pragma unroll
    for (int o = 16; o; o >>= 1) v += __shfl_xor_sync(0xffffffffu, v, o);
    int w = threadIdx.x >> 5;
    __syncthreads();
    if ((threadIdx.x & 31) == 0) s_red[w] = v;
    __syncthreads();
    return s_red[0] + s_red[1];
}

__global__ __launch_bounds__(64) void k_agg_node(
    const int* __restrict__ atom, const float* __restrict__ mask,
    const float* __restrict__ na_w1, const float* __restrict__ na_b1,
    const float* __restrict__ na_w2, const float* __restrict__ na_b2,
    const float* __restrict__ na_w3, const float* __restrict__ na_b3,
    const float* __restrict__ na_g, const float* __restrict__ na_beta,
    const float* __restrict__ edge, float* __restrict__ node_out)
{
    int bj = blockIdx.x;
    int b = bj >> 8, j = bj & 255;
    int c = threadIdx.x;
    __shared__ float s_x[128], s_h[64], s_h2[64], s_red[2];

    float acc = 0.0f, msum = 0.0f;
    const float* ep = edge + (b * 65536 + j) * 64 + c;
    const float* mp = mask + b * 65536 + j;
#pragma unroll 8
    for (int i = 0; i < 256; i++) {
        acc  += ep[i * 16384];
        msum += mp[i * 256];
    }
    float gate = (atom[bj] >= 1) ? 1.0f : 0.0f;
    float nodev = g_node[bj * 64 + c];
    s_x[c]      = nodev;
    s_x[64 + c] = acc / (msum + 1e-10f) * gate;
    __syncthreads();

    float y = na_b1[c];
#pragma unroll 8
    for (int k = 0; k < 128; k++) y += s_x[k] * na_w1[k * 64 + c];
    s_h[c] = fmaxf(y, 0.0f);
    __syncthreads();

    y = na_b2[c];
#pragma unroll 8
    for (int k = 0; k < 64; k++) y += s_h[k] * na_w2[k * 64 + c];
    s_h2[c] = fmaxf(y, 0.0f);
    __syncthreads();

    y = na_b3[c];
#pragma unroll 8
    for (int k = 0; k < 64; k++) y += s_h2[k] * na_w3[k * 64 + c];

    float mean = red64(y, s_red) * (1.0f / 64.0f);
    float d = y - mean;
    float var = red64(d * d, s_red) * (1.0f / 64.0f);
    node_out[bj * 64 + c] = nodev + d * rsqrtf(var + 1e-5f) * na_g[c] + na_beta[c];
}

// ================= launch =================
extern "C" void kernel_launch(void* const* d_in, const int* in_sizes, int n_in,
                              void* d_out, int out_size) {
    (void)in_sizes; (void)n_in; (void)out_size;
    const int*   atom    = (const int*)  d_in[0];
    const float* pos     = (const float*)d_in[1];
    const float* mask    = (const float*)d_in[2];
    const float* emb     = (const float*)d_in[3];
    const float* ne_w    = (const float*)d_in[4];
    const float* ne_b    = (const float*)d_in[5];
    const float* ne_g    = (const float*)d_in[6];
    const float* ne_beta = (const float*)d_in[7];
    const float* ee_w1   = (const float*)d_in[8];
    const float* ee_b1   = (const float*)d_in[9];
    const float* ee_w2   = (const float*)d_in[10];
    const float* ee_b2   = (const float*)d_in[11];
    const float* ee_w3   = (const float*)d_in[12];
    const float* ee_b3   = (const float*)d_in[13];
    const float* ee_g    = (const float*)d_in[14];
    const float* ee_beta = (const float*)d_in[15];
    const float* na_w1   = (const float*)d_in[16];
    const float* na_b1   = (const float*)d_in[17];
    const float* na_w2   = (const float*)d_in[18];
    const float* na_b2   = (const float*)d_in[19];
    const float* na_w3   = (const float*)d_in[20];
    const float* na_b3   = (const float*)d_in[21];
    const float* na_g    = (const float*)d_in[22];
    const float* na_beta = (const float*)d_in[23];

    float* out      = (float*)d_out;
    float* node_out = out;                  // (B,N,D)
    float* edge_out = out + PB * PN * 64;   // (B,N,N,E)

    const int SMEM_EDGE = SMEM_WORDS * 4;   // 110592 B
    cudaFuncSetAttribute(k_edge, cudaFuncAttributeMaxDynamicSharedMemorySize, SMEM_EDGE);

    k_node_prep<<<PB * PN / 4, dim3(64, 4)>>>(atom, emb, ne_w, ne_b, ne_g, ne_beta, ee_w1);
    k_wprep<<<1, 256>>>(ee_w1, ee_w2, ee_w3);
    k_edge<<<PB * PN, 256, SMEM_EDGE>>>(pos, mask, ee_b1, ee_b2, ee_b3,
                                        ee_g, ee_beta, edge_out);
    k_agg_node<<<PB * PN, 64>>>(atom, mask, na_w1, na_b1, na_w2, na_b2,
                                na_w3, na_b3, na_g, na_beta, edge_out, node_out);
}